// round 3
// baseline (speedup 1.0000x reference)
#include <cuda_runtime.h>

#define BB 128
#define TT 152
#define II 75
#define HH 256
#define LL 16
#define CC 625
#define G4 1024
#define EPSV 1e-5f

// ---------------- device scratch (no allocation allowed) ----------------
__device__ float d_wi[(size_t)TT * G4 * BB];   // [t][gate_col][b]
__device__ float d_x0[(size_t)TT * HH * BB];   // k-major: [t][k][b]  (ping)
__device__ float d_x1[(size_t)TT * HH * BB];   // k-major: [t][k][b]  (pong)
__device__ unsigned int d_barc[4];             // per-chunk-group forward counters

__global__ void reset_bar_kernel() {
    d_barc[0] = 0u; d_barc[1] = 0u; d_barc[2] = 0u; d_barc[3] = 0u;
}

__device__ __forceinline__ float sigm(float x) { return 1.f / (1.f + __expf(-x)); }

__device__ __forceinline__ unsigned int ld_acq(const unsigned int* p) {
    unsigned int v;
    asm volatile("ld.global.acquire.gpu.u32 %0, [%1];" : "=r"(v) : "l"(p));
    return v;
}

__device__ __forceinline__ void cp16(float* s, const float* g) {
    unsigned int sa = (unsigned int)__cvta_generic_to_shared(s);
    asm volatile("cp.async.cg.shared.global [%0], [%1], 16;" :: "r"(sa), "l"(g));
}
__device__ __forceinline__ void cp_commit() {
    asm volatile("cp.async.commit_group;");
}
template <int N>
__device__ __forceinline__ void cp_wait() {
    asm volatile("cp.async.wait_group %0;" :: "n"(N));
}

// =====================================================================
// Projection + BatchNorm kernel (at FFMA peak — unchanged):
//   wi = x[t] @ Wi, BN over batch per (t,col), +bias, -> d_wi[t][col][b].
// grid: (T, 16 col-blocks of 64), block 256.
// =====================================================================
__launch_bounds__(256) __global__ void projbn_kernel(
    const float* __restrict__ seq, const float* __restrict__ Wi,
    const float* __restrict__ gih, const float* __restrict__ bih,
    const float* __restrict__ bias, int K, int in_sel)
{
    extern __shared__ float sm[];
    float* xs    = sm;               // [64][129] x chunk, [kk][b]
    float* ws    = sm + 8256;        // [64][65]  W chunk
    float* red_s = ws + 4160;        // [16][64]
    float* red_q = red_s + 1024;     // [16][64]
    float* alpha = red_q + 1024;     // [64]
    float* beta  = alpha + 64;       // [64]
    float* st    = xs;               // alias (reused after GEMM): [64][129]

    const int tid = threadIdx.x;
    const int cg = tid & 15;
    const int bg = tid >> 4;
    const int t = blockIdx.x;
    const int col0 = blockIdx.y * 64;

    float acc[8][4];
#pragma unroll
    for (int i = 0; i < 8; i++)
#pragma unroll
        for (int j = 0; j < 4; j++) acc[i][j] = 0.f;

    for (int k0 = 0; k0 < K; k0 += 64) {
        int kc = K - k0; if (kc > 64) kc = 64;
        if (in_sel < 0) {
            for (int idx = tid; idx < 64 * 128; idx += 256) {
                int kk = idx & 63, b = idx >> 6;
                float v = 0.f;
                if (kk < kc) v = seq[(b * TT + t) * II + (k0 + kk)];
                xs[kk * 129 + b] = v;
            }
        } else {
            const float* src = in_sel ? d_x1 : d_x0;
            for (int idx = tid; idx < 64 * 128; idx += 256) {
                int b = idx & 127, kk = idx >> 7;
                float v = 0.f;
                if (kk < kc) v = src[((size_t)t * HH + (k0 + kk)) * BB + b];
                xs[kk * 129 + b] = v;
            }
        }
        for (int idx = tid; idx < 64 * 64; idx += 256) {
            int c = idx & 63, kk = idx >> 6;
            ws[kk * 65 + c] = (kk < kc) ? Wi[(k0 + kk) * G4 + col0 + c] : 0.f;
        }
        __syncthreads();
#pragma unroll 4
        for (int kk = 0; kk < 64; kk++) {
            float w0 = ws[kk * 65 + cg * 4 + 0];
            float w1 = ws[kk * 65 + cg * 4 + 1];
            float w2 = ws[kk * 65 + cg * 4 + 2];
            float w3 = ws[kk * 65 + cg * 4 + 3];
#pragma unroll
            for (int i = 0; i < 8; i++) {
                float xv = xs[kk * 129 + bg * 8 + i];
                acc[i][0] += xv * w0;
                acc[i][1] += xv * w1;
                acc[i][2] += xv * w2;
                acc[i][3] += xv * w3;
            }
        }
        __syncthreads();
    }

#pragma unroll
    for (int j = 0; j < 4; j++) {
        float ls = 0.f, lq = 0.f;
#pragma unroll
        for (int i = 0; i < 8; i++) { ls += acc[i][j]; lq += acc[i][j] * acc[i][j]; }
        red_s[bg * 64 + cg * 4 + j] = ls;
        red_q[bg * 64 + cg * 4 + j] = lq;
    }
    __syncthreads();
    if (tid < 64) {
        float s = 0.f, q = 0.f;
        for (int g = 0; g < 16; g++) { s += red_s[g * 64 + tid]; q += red_q[g * 64 + tid]; }
        float mean = s * (1.f / 128.f);
        float var  = q * (1.f / 128.f) - mean * mean;
        float rs = rsqrtf(var + EPSV);
        int col = col0 + tid;
        float a = gih[col] * rs;
        alpha[tid] = a;
        beta[tid] = bih[col] + bias[col] - mean * a;
    }
    __syncthreads();
#pragma unroll
    for (int j = 0; j < 4; j++)
#pragma unroll
        for (int i = 0; i < 8; i++)
            st[(cg * 4 + j) * 129 + (bg * 8 + i)] = acc[i][j];
    __syncthreads();
    for (int idx = tid; idx < 64 * 128; idx += 256) {
        int b = idx & 127, c = idx >> 7;
        d_wi[((size_t)t * G4 + col0 + c) * BB + b] = st[c * 129 + b] * alpha[c] + beta[c];
    }
}

// =====================================================================
// Persistent recurrence: forward-only dataflow sync (NO global barrier).
// 128 CTAs; CTA bid owns h-cols {2bid, 2bid+1}; producer group g = bid>>5
// covers k-range [64g, 64g+64). After storing h(t), CTA arrives on
// d_barc[g] (release). A consumer fills chunk c of h(t-1) once
// d_barc[c] >= 32*t. Chunk fills are cp.async double-buffered under GEMM.
// =====================================================================
__launch_bounds__(256, 1) __global__ void recur_kernel(
    const float* __restrict__ Whh_l,
    const float* __restrict__ ghh_l, const float* __restrict__ bhh_l,
    const float* __restrict__ gc_l,  const float* __restrict__ bc_l,
    int out_sel)
{
    extern __shared__ float sm[];
    float* hbuf = sm;                     // [2][64][132] h chunk double buffer
    float* wsm  = sm + 2 * 64 * 132;      // [256][8]    Whh slice
    float* red  = wsm + 2048;             // reduction scratch

    float* hsout = out_sel ? d_x1 : d_x0;   // k-major [t][k][b]

    const int tid = threadIdx.x;
    const int hcl = tid >> 7;
    const int b   = tid & 127;
    const int warp = tid >> 5, lane = tid & 31;
    const int hcol = blockIdx.x * 2 + hcl;
    const int f4 = tid & 31;
    const int mygrp = blockIdx.x >> 5;

    for (int idx = tid; idx < 256 * 8; idx += 256) {
        int k = idx >> 3, q = idx & 7;
        int hc = blockIdx.x * 2 + (q >> 2);
        int j = q & 3;
        wsm[idx] = Whh_l[k * G4 + j * HH + hc];
    }

    float ghh[4], bhh[4];
#pragma unroll
    for (int j = 0; j < 4; j++) {
        ghh[j] = ghh_l[j * HH + hcol];
        bhh[j] = bhh_l[j * HH + hcol];
    }
    const float gcv = gc_l[hcol], bcv = bc_l[hcol];
    float c = 0.f;

    __syncthreads();

    const float4* w4 = (const float4*)wsm;
    float* b0 = hbuf;
    float* b1 = hbuf + 64 * 132;

    for (int t = 0; t < TT; t++) {
        // this step's bn_wi (L2-resident, overlaps with fills/GEMM)
        float wiv[4];
#pragma unroll
        for (int j = 0; j < 4; j++)
            wiv[j] = d_wi[((size_t)t * G4 + j * HH + hcol) * BB + b];

        float acc[4] = {0.f, 0.f, 0.f, 0.f};
        if (t > 0) {
            const float* hprev = hsout + (size_t)(t - 1) * HH * BB;
            const unsigned int tgt = 32u * (unsigned)t;

            // ---- wait for chunk c's producer group, then cp.async fill ----
#define WAITC(cidx)                                                     \
            do { if (tid == 0) { while (ld_acq(&d_barc[cidx]) < tgt) {} } \
                 __syncthreads(); } while (0)
#define FILLC(cidx, dst)                                                \
            do { _Pragma("unroll")                                      \
                 for (int i = 0; i < 8; i++) {                          \
                     int kk = warp + 8 * i;                             \
                     cp16((dst) + kk * 132 + f4 * 4,                    \
                          hprev + ((cidx) * 64 + kk) * BB + f4 * 4);    \
                 } cp_commit(); } while (0)
#define COMPC(kbase, buf)                                               \
            do { const float* hc_ = (buf);                              \
                 _Pragma("unroll 8")                                    \
                 for (int kk = 0; kk < 64; kk++) {                      \
                     float hv = hc_[kk * 132 + b];                      \
                     float4 w = w4[((kbase) + kk) * 2 + hcl];           \
                     acc[0] += hv * w.x;  acc[1] += hv * w.y;           \
                     acc[2] += hv * w.z;  acc[3] += hv * w.w;           \
                 } } while (0)

            WAITC(0);  FILLC(0, b0);
            WAITC(1);  FILLC(1, b1);
            cp_wait<1>(); __syncthreads();
            COMPC(0, b0);
            WAITC(2);  FILLC(2, b0);     // WAITC's bar also drains b0 readers
            cp_wait<1>(); __syncthreads();
            COMPC(64, b1);
            WAITC(3);  FILLC(3, b1);
            cp_wait<1>(); __syncthreads();
            COMPC(128, b0);
            cp_wait<0>(); __syncthreads();
            COMPC(192, b1);
#undef WAITC
#undef FILLC
#undef COMPC
        }

        // ---- BN over batch per gate column ----
        float s[4], q[4];
#pragma unroll
        for (int j = 0; j < 4; j++) { s[j] = acc[j]; q[j] = acc[j] * acc[j]; }
#pragma unroll
        for (int o = 16; o; o >>= 1)
#pragma unroll
            for (int j = 0; j < 4; j++) {
                s[j] += __shfl_xor_sync(0xffffffffu, s[j], o);
                q[j] += __shfl_xor_sync(0xffffffffu, q[j], o);
            }
        if (lane == 0)
#pragma unroll
            for (int j = 0; j < 4; j++) {
                red[warp * 8 + j] = s[j];
                red[warp * 8 + 4 + j] = q[j];
            }
        __syncthreads();
        float sg[4];
        {
            float S[4] = {0,0,0,0}, Q[4] = {0,0,0,0};
            int w0 = hcl * 4;
#pragma unroll
            for (int w = 0; w < 4; w++)
#pragma unroll
                for (int j = 0; j < 4; j++) {
                    S[j] += red[(w0 + w) * 8 + j];
                    Q[j] += red[(w0 + w) * 8 + 4 + j];
                }
#pragma unroll
            for (int j = 0; j < 4; j++) {
                float mean = S[j] * (1.f / 128.f);
                float var = Q[j] * (1.f / 128.f) - mean * mean;
                float rs = rsqrtf(var + EPSV);
                sg[j] = (acc[j] - mean) * rs * ghh[j] + bhh[j] + wiv[j];
            }
        }
        // gate order: f, i, o, g
        float fg = sigm(sg[0]);
        float ig = sigm(sg[1]);
        float og = sigm(sg[2]);
        float gg = tanhf(sg[3]);
        c = fg * c + ig * gg;

        // ---- BN(c) over batch ----
        float cs = c, cq = c * c;
#pragma unroll
        for (int o = 16; o; o >>= 1) {
            cs += __shfl_xor_sync(0xffffffffu, cs, o);
            cq += __shfl_xor_sync(0xffffffffu, cq, o);
        }
        if (lane == 0) { red[64 + warp * 2] = cs; red[64 + warp * 2 + 1] = cq; }
        __syncthreads();
        float Sc = 0.f, Qc = 0.f;
        {
            int w0 = hcl * 4;
#pragma unroll
            for (int w = 0; w < 4; w++) { Sc += red[64 + (w0 + w) * 2]; Qc += red[64 + (w0 + w) * 2 + 1]; }
        }
        float mc = Sc * (1.f / 128.f);
        float vc = Qc * (1.f / 128.f) - mc * mc;
        float cn = (c - mc) * rsqrtf(vc + EPSV) * gcv + bcv;
        float h = og * tanhf(cn);

        // coalesced k-major store, then release-arrive on own group counter
        hsout[(size_t)t * HH * BB + hcol * BB + b] = h;
        __syncthreads();
        if (t < TT - 1 && tid == 0) {
            __threadfence();
            atomicAdd(&d_barc[mygrp], 1u);
        }
    }
}

// =====================================================================
// Final: out = softmax(h_last @ W_lin + b_lin). grid 128 (batch), block 256.
// =====================================================================
__launch_bounds__(256) __global__ void final_kernel(
    int xsel, const float* __restrict__ Wlin, const float* __restrict__ blin,
    float* __restrict__ out)
{
    __shared__ float xr[256];
    __shared__ float lg[CC];
    __shared__ float rbuf[8];
    const float* hs = (xsel ? d_x1 : d_x0);
    int tid = threadIdx.x, warp = tid >> 5, lane = tid & 31;

    xr[tid] = hs[(size_t)(TT - 1) * HH * BB + tid * BB + blockIdx.x];
    __syncthreads();

    float lmax = -1e30f;
    for (int cidx = tid; cidx < CC; cidx += 256) {
        float a = blin[cidx];
#pragma unroll 4
        for (int k = 0; k < 256; k++) a += xr[k] * Wlin[k * CC + cidx];
        lg[cidx] = a;
        lmax = fmaxf(lmax, a);
    }
#pragma unroll
    for (int o = 16; o; o >>= 1) lmax = fmaxf(lmax, __shfl_xor_sync(0xffffffffu, lmax, o));
    if (lane == 0) rbuf[warp] = lmax;
    __syncthreads();
    float M = rbuf[0];
#pragma unroll
    for (int w = 1; w < 8; w++) M = fmaxf(M, rbuf[w]);
    __syncthreads();

    float lsum = 0.f;
    for (int cidx = tid; cidx < CC; cidx += 256) {
        float e = __expf(lg[cidx] - M);
        lg[cidx] = e;
        lsum += e;
    }
#pragma unroll
    for (int o = 16; o; o >>= 1) lsum += __shfl_xor_sync(0xffffffffu, lsum, o);
    if (lane == 0) rbuf[warp] = lsum;
    __syncthreads();
    float S = 0.f;
#pragma unroll
    for (int w = 0; w < 8; w++) S += rbuf[w];
    float inv = 1.f / S;
    for (int cidx = tid; cidx < CC; cidx += 256)
        out[blockIdx.x * CC + cidx] = lg[cidx] * inv;
}

// =====================================================================
extern "C" void kernel_launch(void* const* d_in, const int* in_sizes, int n_in,
                              void* d_out, int out_size)
{
    const float* seq  = (const float*)d_in[0];
    const float* Wih0 = (const float*)d_in[1];
    const float* Wih  = (const float*)d_in[2];
    const float* Whh  = (const float*)d_in[3];
    const float* bias = (const float*)d_in[4];
    const float* gih  = (const float*)d_in[5];
    const float* bih  = (const float*)d_in[6];
    const float* ghh  = (const float*)d_in[7];
    const float* bhh  = (const float*)d_in[8];
    const float* gc   = (const float*)d_in[9];
    const float* bc   = (const float*)d_in[10];
    const float* Wlin = (const float*)d_in[11];
    const float* blin = (const float*)d_in[12];
    float* out = (float*)d_out;

    const int PROJ_SMEM  = (8256 + 4160 + 1024 + 1024 + 64 + 64) * 4;   // 58368 B
    const int RECUR_SMEM = (2 * 64 * 132 + 2048 + 96) * 4;              // 76160 B

    cudaFuncSetAttribute((const void*)projbn_kernel,
                         cudaFuncAttributeMaxDynamicSharedMemorySize, PROJ_SMEM);
    cudaFuncSetAttribute((const void*)recur_kernel,
                         cudaFuncAttributeMaxDynamicSharedMemorySize, RECUR_SMEM);

    for (int l = 0; l < LL; l++) {
        const float* Wi = (l == 0) ? Wih0 : (Wih + (size_t)(l - 1) * HH * G4);
        int K = (l == 0) ? II : HH;
        int in_sel = (l == 0) ? -1 : ((l - 1) & 1);
        projbn_kernel<<<dim3(TT, 16), 256, PROJ_SMEM>>>(
            seq, Wi, gih + l * G4, bih + l * G4, bias + l * G4, K, in_sel);
        reset_bar_kernel<<<1, 1>>>();
        recur_kernel<<<128, 256, RECUR_SMEM>>>(
            Whh + (size_t)l * HH * G4,
            ghh + l * G4, bhh + l * G4, gc + l * HH, bc + l * HH, l & 1);
    }
    final_kernel<<<128, 256>>>((LL - 1) & 1, Wlin, blin, out);
}

// round 4
// speedup vs baseline: 1.4726x; 1.4726x over previous
#include <cuda_runtime.h>

#define BB 128
#define TT 152
#define II 75
#define HH 256
#define LL 16
#define CC 625
#define G4 1024
#define EPSV 1e-5f
#define DD 8          // h ring depth (timesteps)
#define GRP 8         // CTAs per layer group

// ---------------- device scratch (no allocation allowed) ----------------
__device__ float d_xseq[(size_t)TT * 256 * BB];        // [t][k256 pad][b]  ~20MB
__device__ float d_hring[(size_t)LL * DD * HH * BB];   // [l][slot][k][b]   ~17MB
__device__ float d_Wir[(size_t)LL * G4 * 256];         // [l][rank][sub][k][64]
__device__ float d_Whr[(size_t)LL * G4 * 256];         // same layout
__device__ unsigned int d_cnt[LL + 1];                 // cnt[l+1] = steps done by group l (x GRP)

__device__ __forceinline__ float sigm(float x) { return 1.f / (1.f + __expf(-x)); }

__device__ __forceinline__ float wsum(float v) {
#pragma unroll
    for (int o = 16; o; o >>= 1) v += __shfl_xor_sync(0xffffffffu, v, o);
    return v;
}

__device__ __forceinline__ unsigned int ld_acq(const unsigned int* p) {
    unsigned int v;
    asm volatile("ld.global.acquire.gpu.u32 %0, [%1];" : "=r"(v) : "l"(p));
    return v;
}
__device__ __forceinline__ void arrive_rel(unsigned int* p) {
    asm volatile("red.release.gpu.global.add.u32 [%0], 1;" :: "l"(p) : "memory");
}
__device__ __forceinline__ void cp16(float* s, const float* g) {
    unsigned int sa = (unsigned int)__cvta_generic_to_shared(s);
    asm volatile("cp.async.cg.shared.global [%0], [%1], 16;" :: "r"(sa), "l"(g));
}
__device__ __forceinline__ void cp_commit() { asm volatile("cp.async.commit_group;"); }
template <int N>
__device__ __forceinline__ void cp_wait() { asm volatile("cp.async.wait_group %0;" :: "n"(N)); }

// =====================================================================
// Pre-pass kernels (run every launch; cheap, deterministic)
// =====================================================================
__global__ void prep_reset() {
    int i = threadIdx.x;
    if (i <= LL) d_cnt[i] = (i == 0) ? 0x40000000u : 0u;
}

// sequences [b][t][75] -> d_xseq [t][k(256, zero pad)][b]
__global__ void prep_xseq(const float* __restrict__ seq) {
    __shared__ float tsm[II * 129];
    int t = blockIdx.x, tid = threadIdx.x;
    for (int idx = tid; idx < BB * II; idx += 256) {
        int b = idx / II, k = idx - b * II;
        tsm[k * 129 + b] = seq[(b * TT + t) * II + k];
    }
    __syncthreads();
    float* dst = d_xseq + (size_t)t * (256 * BB);
    for (int idx = tid; idx < 256 * BB; idx += 256) {
        int k = idx >> 7, b = idx & 127;
        dst[idx] = (k < II) ? tsm[k * 129 + b] : 0.f;
    }
}

// Reshape W_ih/W_hh into per-(layer,rank,sub) streaming layout [k][hcig*4+g]
__global__ void prep_w(const float* __restrict__ Wih0, const float* __restrict__ Wih,
                       const float* __restrict__ Whh) {
    int l = blockIdx.x, rank = blockIdx.y, tid = threadIdx.x;
    size_t dbase = (((size_t)l * GRP + rank) * 2) * (256 * 64);
    for (int idx = tid; idx < 32768; idx += 256) {
        int k = idx >> 7, r7 = idx & 127;
        int g = r7 >> 5, rq = r7 & 31;
        int hcig = rq & 15, sub = rq >> 4;
        int col = g * 256 + rank * 32 + rq;
        float vi;
        if (l == 0) vi = (k < II) ? Wih0[k * G4 + col] : 0.f;
        else        vi = Wih[((size_t)(l - 1) * HH + k) * G4 + col];
        float vh = Whh[((size_t)l * HH + k) * G4 + col];
        size_t doff = dbase + ((size_t)sub * 256 + k) * 64 + hcig * 4 + g;
        d_Wir[doff] = vi;
        d_Whr[doff] = vh;
    }
}

// =====================================================================
// One GEMM phase: acc[32] += sum_{k<256} src[k][b] * W[k][hcl*32 .. +31]
// src global [256][128], Wsrc global [256][64]; double-buffered cp.async.
// Ends with a __syncthreads() (buffers free for next phase).
// =====================================================================
__device__ __forceinline__ void gemm_phase(
    float* acc, const float* __restrict__ src, const float* __restrict__ Wsrc,
    float* xs0, float* xs1, float* wb0, float* wb1, int tid, int b, int hcl)
{
#pragma unroll
    for (int cc = 0; cc < 2; cc++) {
        float* xd = cc ? xs1 : xs0;
        float* wd = cc ? wb1 : wb0;
#pragma unroll
        for (int i = 0; i < 8; i++) {
            int f = tid + i * 256, kk = f >> 5, bq = f & 31;
            cp16(xd + kk * 132 + bq * 4, src + (cc * 64 + kk) * 128 + bq * 4);
        }
#pragma unroll
        for (int i = 0; i < 4; i++) {
            int f = tid + i * 256, kk = f >> 4, lq = f & 15;
            cp16(wd + kk * 64 + lq * 4, Wsrc + (cc * 64 + kk) * 64 + lq * 4);
        }
        cp_commit();
    }
#pragma unroll
    for (int cc = 0; cc < 4; cc++) {
        if (cc < 3) cp_wait<1>(); else cp_wait<0>();
        __syncthreads();
        const float* xs = (cc & 1) ? xs1 : xs0;
        const float* wb = (cc & 1) ? wb1 : wb0;
#pragma unroll 2
        for (int k = 0; k < 64; k++) {
            float hv = xs[k * 132 + b];
            const float4* wr = (const float4*)(wb + k * 64 + hcl * 32);
#pragma unroll
            for (int i = 0; i < 8; i++) {
                float4 w = wr[i];
                acc[i * 4 + 0] += hv * w.x;
                acc[i * 4 + 1] += hv * w.y;
                acc[i * 4 + 2] += hv * w.z;
                acc[i * 4 + 3] += hv * w.w;
            }
        }
        if (cc < 2) {
            __syncthreads();
            int c2 = cc + 2;
            float* xd = (cc & 1) ? xs1 : xs0;
            float* wd = (cc & 1) ? wb1 : wb0;
#pragma unroll
            for (int i = 0; i < 8; i++) {
                int f = tid + i * 256, kk = f >> 5, bq = f & 31;
                cp16(xd + kk * 132 + bq * 4, src + (c2 * 64 + kk) * 128 + bq * 4);
            }
#pragma unroll
            for (int i = 0; i < 4; i++) {
                int f = tid + i * 256, kk = f >> 4, lq = f & 15;
                cp16(wd + kk * 64 + lq * 4, Wsrc + (c2 * 64 + kk) * 64 + lq * 4);
            }
            cp_commit();
        }
    }
    __syncthreads();
}

// =====================================================================
// Wavefront kernel: 16 layer groups x 8 CTAs, all co-resident.
// Group l, rank r owns hcols [r*32, r*32+32); 2 subtiles of 16 hcols.
// =====================================================================
__launch_bounds__(256, 1) __global__ void wave_kernel(
    const float* __restrict__ ghh, const float* __restrict__ bhh,
    const float* __restrict__ gih, const float* __restrict__ bih,
    const float* __restrict__ bias,
    const float* __restrict__ gc,  const float* __restrict__ bc)
{
    extern __shared__ float sm[];
    float* xs0 = sm;                  // 64*132
    float* xs1 = sm + 8448;
    float* wb0 = sm + 16896;          // 64*64
    float* wb1 = sm + 20992;
    float* red = sm + 25088;          // 4*256
    float* ab  = sm + 26112;          // 192

    const int tid = threadIdx.x;
    const int warp = tid >> 5, lane = tid & 31;
    const int b = tid & 127;
    const int hcl = tid >> 7;
    const int l = blockIdx.x >> 3;
    const int rank = blockIdx.x & 7;

    const float* ghh_p = ghh + l * G4;
    const float* bhh_p = bhh + l * G4;
    const float* gih_p = gih + l * G4;
    const float* bih_p = bih + l * G4;
    const float* bias_p = bias + l * G4;
    const float* gc_p = gc + l * HH;
    const float* bc_p = bc + l * HH;

    float cr[16];
#pragma unroll
    for (int i = 0; i < 16; i++) cr[i] = 0.f;

    for (int t = 0; t < TT; t++) {
        // step-start waits: backpressure + own-group previous step
        if (tid == 0) {
            if (l < LL - 1 && t >= DD)
                while (ld_acq(&d_cnt[l + 2]) < (unsigned)(GRP * (t - DD + 1))) {}
            if (t > 0)
                while (ld_acq(&d_cnt[l + 1]) < (unsigned)(GRP * t)) {}
        }
        __syncthreads();

        const float* xsrc = (l == 0)
            ? d_xseq + (size_t)t * (256 * BB)
            : d_hring + ((size_t)(l - 1) * DD + (t & (DD - 1))) * (HH * BB);
        const float* hsrc = d_hring + ((size_t)l * DD + ((t - 1) & (DD - 1))) * (HH * BB);
        float* hdst = d_hring + ((size_t)l * DD + (t & (DD - 1))) * (HH * BB);

        bool xwaited = (l == 0);

#pragma unroll 1
        for (int sub = 0; sub < 2; sub++) {
            float aw[32], ai[32];
#pragma unroll
            for (int x = 0; x < 32; x++) { aw[x] = 0.f; ai[x] = 0.f; }

            const float* whh_p = d_Whr + ((((size_t)l * GRP + rank) * 2 + sub) * (256 * 64));
            const float* wih_p = d_Wir + ((((size_t)l * GRP + rank) * 2 + sub) * (256 * 64));

            // phase B: recurrence GEMM (own h(t-1)) — no external wait
            if (t > 0)
                gemm_phase(aw, hsrc, whh_p, xs0, xs1, wb0, wb1, tid, b, hcl);

            // phase A: input projection GEMM — wait producer once per step
            if (!xwaited) {
                if (tid == 0)
                    while (ld_acq(&d_cnt[l]) < (unsigned)(GRP * (t + 1))) {}
                __syncthreads();
                xwaited = true;
            }
            gemm_phase(ai, xsrc, wih_p, xs0, xs1, wb0, wb1, tid, b, hcl);

            // ---- BN stats over batch for 32 gate cols (wh) + 32 (wi) ----
#pragma unroll
            for (int x = 0; x < 32; x++) {
                float s = wsum(aw[x]);
                if (lane == 0) red[0 * 256 + warp * 32 + x] = s;
                float q = wsum(aw[x] * aw[x]);
                if (lane == 0) red[1 * 256 + warp * 32 + x] = q;
                float si = wsum(ai[x]);
                if (lane == 0) red[2 * 256 + warp * 32 + x] = si;
                float qi = wsum(ai[x] * ai[x]);
                if (lane == 0) red[3 * 256 + warp * 32 + x] = qi;
            }
            __syncthreads();
            if (tid < 64) {
                int g = tid & 3, hcig = tid >> 2;
                int w0 = (hcig >> 3) * 4;
                int x = (hcig & 7) * 4 + g;
                float Sh = 0, Qh = 0, Si = 0, Qi = 0;
#pragma unroll
                for (int w = 0; w < 4; w++) {
                    Sh += red[0 * 256 + (w0 + w) * 32 + x];
                    Qh += red[1 * 256 + (w0 + w) * 32 + x];
                    Si += red[2 * 256 + (w0 + w) * 32 + x];
                    Qi += red[3 * 256 + (w0 + w) * 32 + x];
                }
                float mh = Sh * (1.f / 128.f);
                float vh = Qh * (1.f / 128.f) - mh * mh;
                float rsh = rsqrtf(vh + EPSV);
                float mi = Si * (1.f / 128.f);
                float vi = Qi * (1.f / 128.f) - mi * mi;
                float rsi = rsqrtf(vi + EPSV);
                int colg = g * 256 + rank * 32 + sub * 16 + hcig;
                float ah = ghh_p[colg] * rsh;
                float aiC = gih_p[colg] * rsi;
                float bsum = bhh_p[colg] - mh * ah + bih_p[colg] - mi * aiC + bias_p[colg];
                ab[tid * 3 + 0] = ah;
                ab[tid * 3 + 1] = aiC;
                ab[tid * 3 + 2] = bsum;
            }
            __syncthreads();

            float og[8];
#pragma unroll
            for (int i = 0; i < 8; i++) {
                int lc = (hcl * 8 + i) * 4;
                float s0 = ab[(lc + 0) * 3] * aw[i * 4 + 0] + ab[(lc + 0) * 3 + 1] * ai[i * 4 + 0] + ab[(lc + 0) * 3 + 2];
                float s1 = ab[(lc + 1) * 3] * aw[i * 4 + 1] + ab[(lc + 1) * 3 + 1] * ai[i * 4 + 1] + ab[(lc + 1) * 3 + 2];
                float s2 = ab[(lc + 2) * 3] * aw[i * 4 + 2] + ab[(lc + 2) * 3 + 1] * ai[i * 4 + 2] + ab[(lc + 2) * 3 + 2];
                float s3 = ab[(lc + 3) * 3] * aw[i * 4 + 3] + ab[(lc + 3) * 3 + 1] * ai[i * 4 + 3] + ab[(lc + 3) * 3 + 2];
                float fg = sigm(s0);
                float ig = sigm(s1);
                og[i] = sigm(s2);
                float gg = tanhf(s3);
                cr[sub * 8 + i] = fg * cr[sub * 8 + i] + ig * gg;
            }

            // ---- BN(c) over batch for 16 h cols ----
#pragma unroll
            for (int i = 0; i < 8; i++) {
                float cv = cr[sub * 8 + i];
                float s = wsum(cv);
                float q = wsum(cv * cv);
                if (lane == 0) {
                    red[warp * 32 + i * 2] = s;
                    red[warp * 32 + i * 2 + 1] = q;
                }
            }
            __syncthreads();
            if (tid < 16) {
                int hcig = tid, w0 = (hcig >> 3) * 4;
                float S = 0, Q = 0;
#pragma unroll
                for (int w = 0; w < 4; w++) {
                    S += red[(w0 + w) * 32 + (hcig & 7) * 2];
                    Q += red[(w0 + w) * 32 + (hcig & 7) * 2 + 1];
                }
                float m = S * (1.f / 128.f);
                float v = Q * (1.f / 128.f) - m * m;
                float rs = rsqrtf(v + EPSV);
                int hcolg = rank * 32 + sub * 16 + hcig;
                float ac = gc_p[hcolg] * rs;
                ab[tid * 2] = ac;
                ab[tid * 2 + 1] = bc_p[hcolg] - m * ac;
            }
            __syncthreads();

            float* hout = hdst + (rank * 32 + sub * 16) * BB;
#pragma unroll
            for (int i = 0; i < 8; i++) {
                int hc = hcl * 8 + i;
                float cn = ab[hc * 2] * cr[sub * 8 + i] + ab[hc * 2 + 1];
                hout[hc * BB + b] = og[i] * tanhf(cn);
            }
            __syncthreads();
        }

        __threadfence();
        __syncthreads();
        if (tid == 0) arrive_rel(&d_cnt[l + 1]);
    }
}

// =====================================================================
// Final: out = softmax(h15(T-1) @ W_lin + b_lin). grid 128 (batch), block 256.
// =====================================================================
__launch_bounds__(256) __global__ void final_kernel(
    const float* __restrict__ Wlin, const float* __restrict__ blin,
    float* __restrict__ out)
{
    __shared__ float xr[256];
    __shared__ float lg[CC];
    __shared__ float rbuf[8];
    const float* hs = d_hring + ((size_t)(LL - 1) * DD + ((TT - 1) & (DD - 1))) * (HH * BB);
    int tid = threadIdx.x, warp = tid >> 5, lane = tid & 31;

    xr[tid] = hs[tid * BB + blockIdx.x];
    __syncthreads();

    float lmax = -1e30f;
    for (int cidx = tid; cidx < CC; cidx += 256) {
        float a = blin[cidx];
#pragma unroll 4
        for (int k = 0; k < 256; k++) a += xr[k] * Wlin[k * CC + cidx];
        lg[cidx] = a;
        lmax = fmaxf(lmax, a);
    }
#pragma unroll
    for (int o = 16; o; o >>= 1) lmax = fmaxf(lmax, __shfl_xor_sync(0xffffffffu, lmax, o));
    if (lane == 0) rbuf[warp] = lmax;
    __syncthreads();
    float M = rbuf[0];
#pragma unroll
    for (int w = 1; w < 8; w++) M = fmaxf(M, rbuf[w]);
    __syncthreads();

    float lsum = 0.f;
    for (int cidx = tid; cidx < CC; cidx += 256) {
        float e = __expf(lg[cidx] - M);
        lg[cidx] = e;
        lsum += e;
    }
#pragma unroll
    for (int o = 16; o; o >>= 1) lsum += __shfl_xor_sync(0xffffffffu, lsum, o);
    if (lane == 0) rbuf[warp] = lsum;
    __syncthreads();
    float S = 0.f;
#pragma unroll
    for (int w = 0; w < 8; w++) S += rbuf[w];
    float inv = 1.f / S;
    for (int cidx = tid; cidx < CC; cidx += 256)
        out[blockIdx.x * CC + cidx] = lg[cidx] * inv;
}

// =====================================================================
extern "C" void kernel_launch(void* const* d_in, const int* in_sizes, int n_in,
                              void* d_out, int out_size)
{
    const float* seq  = (const float*)d_in[0];
    const float* Wih0 = (const float*)d_in[1];
    const float* Wih  = (const float*)d_in[2];
    const float* Whh  = (const float*)d_in[3];
    const float* bias = (const float*)d_in[4];
    const float* gih  = (const float*)d_in[5];
    const float* bih  = (const float*)d_in[6];
    const float* ghh  = (const float*)d_in[7];
    const float* bhh  = (const float*)d_in[8];
    const float* gc   = (const float*)d_in[9];
    const float* bc   = (const float*)d_in[10];
    const float* Wlin = (const float*)d_in[11];
    const float* blin = (const float*)d_in[12];
    float* out = (float*)d_out;

    const int SMEM_WAVE = 122880;   // 105.2KB used; padded to force 1 CTA/SM

    cudaFuncSetAttribute((const void*)wave_kernel,
                         cudaFuncAttributeMaxDynamicSharedMemorySize, SMEM_WAVE);

    prep_reset<<<1, 32>>>();
    prep_xseq<<<TT, 256>>>(seq);
    prep_w<<<dim3(LL, GRP), 256>>>(Wih0, Wih, Whh);
    wave_kernel<<<LL * GRP, 256, SMEM_WAVE>>>(ghh, bhh, gih, bih, bias, gc, bc);
    final_kernel<<<BB, 256>>>(Wlin, blin, out);
}